// round 16
// baseline (speedup 1.0000x reference)
#include <cuda_runtime.h>
#include <cuda_bf16.h>
#include <cstddef>

#define BB 32
#define TT 2048
#define DD 512
#define HH 512
#define G4 2048
#define NCTA 128
#define JC 4
#define NTHR 256
#define GST 136

// Scratch (device globals are the sanctioned allocation-free scratch)
__device__ float g_i2h[(size_t)BB * TT * G4];        // 512 MB, layer-0 i2h
__device__ unsigned short g_h0h[2][BB * HH];         // h0 bf16 hi, [b][k]
__device__ unsigned short g_h0l[2][BB * HH];         // h0 bf16 lo
__device__ unsigned short g_h1h[2][BB * HH];         // h1 bf16 hi
__device__ unsigned short g_h1l[2][BB * HH];         // h1 bf16 lo
__device__ unsigned g_flags[NCTA * 32];              // per-CTA arrival flags

__global__ void init_state_kernel() {
    int i = blockIdx.x * blockDim.x + threadIdx.x;
    if (i < BB * HH) {
        g_h0h[0][i] = 0; g_h0l[0][i] = 0;
        g_h1h[0][i] = 0; g_h1l[0][i] = 0;
    }
    if (i < NCTA * 32) g_flags[i] = 0u;
}

__device__ __forceinline__ float sigf(float x) { return 1.f / (1.f + __expf(-x)); }
__device__ __forceinline__ float tanhf_(float x) {
    x = fminf(15.f, fmaxf(-15.f, x));
    float e = __expf(2.f * x);
    return (e - 1.f) / (e + 1.f);
}

union BFU { __nv_bfloat16 b; unsigned short u; };
__device__ __forceinline__ void bf_split(float v, unsigned short& hi, unsigned short& lo) {
    BFU h; h.b = __float2bfloat16_rn(v);
    BFU l; l.b = __float2bfloat16_rn(v - __bfloat162float(h.b));
    hi = h.u; lo = l.u;
}
__device__ __forceinline__ unsigned bf_pack(unsigned short lo16, unsigned short hi16) {
    return (unsigned)lo16 | ((unsigned)hi16 << 16);
}

__device__ __forceinline__ void mma_bf16(float* d, const unsigned* a, const unsigned* b) {
    asm volatile(
        "mma.sync.aligned.m16n8k16.row.col.f32.bf16.bf16.f32 "
        "{%0,%1,%2,%3}, {%4,%5,%6,%7}, {%8,%9}, {%0,%1,%2,%3};"
        : "+f"(d[0]), "+f"(d[1]), "+f"(d[2]), "+f"(d[3])
        : "r"(a[0]), "r"(a[1]), "r"(a[2]), "r"(a[3]), "r"(b[0]), "r"(b[1]));
}

// C[M,2048] = A[M,512] @ W[2048,512]^T + bias via 3-term bf16 tensor MMA.
// m16n8k16: 2x MACs/instr vs the tf32 path at identical fragment shapes.
__global__ __launch_bounds__(256) void gemm_bf16_kernel(
    const float* __restrict__ A, const float* __restrict__ W,
    const float* __restrict__ bias, float* __restrict__ C)
{
    extern __shared__ unsigned gsmu[];
    unsigned* Ah2 = gsmu;                 // [16 pairs][GST], packed bf16x2 hi
    unsigned* Al2 = Ah2 + 16 * GST;       // lo residual pairs
    unsigned* Wh2 = Al2 + 16 * GST;
    unsigned* Wl2 = Wh2 + 16 * GST;

    const int tid  = threadIdx.x;
    const int lane = tid & 31;
    const int w    = tid >> 5;
    const int wm   = w >> 2;              // 0..1 -> m offset wm*64
    const int wn   = w & 3;               // 0..3 -> n offset wn*32
    const int lg   = lane >> 2;           // 0..7
    const int lt   = lane & 3;            // 0..3
    const int m0   = blockIdx.y * 128;
    const int n0   = blockIdx.x * 128;

    const int mr = tid >> 1;              // staging row 0..127
    const int kq = (tid & 1) << 4;        // staging k base 0|16
    const float* Arow = A + (size_t)(m0 + mr) * DD;
    const float* Wrow = W + (size_t)(n0 + mr) * DD;

    float acc[4][4][4];
    #pragma unroll
    for (int mt = 0; mt < 4; mt++)
        #pragma unroll
        for (int nt = 0; nt < 4; nt++)
            #pragma unroll
            for (int i = 0; i < 4; i++) acc[mt][nt][i] = 0.f;

    for (int kc = 0; kc < DD; kc += 32) {
        __syncthreads();
        #pragma unroll
        for (int i = 0; i < 4; i++) {
            const int kk = kq + 4 * i;
            const int p2 = kk >> 1;
            float4 va = *reinterpret_cast<const float4*>(Arow + kc + kk);
            float4 vw = *reinterpret_cast<const float4*>(Wrow + kc + kk);
            unsigned short h0_, l0_, h1_, l1_;
            bf_split(va.x, h0_, l0_); bf_split(va.y, h1_, l1_);
            Ah2[p2 * GST + mr]       = bf_pack(h0_, h1_);
            Al2[p2 * GST + mr]       = bf_pack(l0_, l1_);
            bf_split(va.z, h0_, l0_); bf_split(va.w, h1_, l1_);
            Ah2[(p2 + 1) * GST + mr] = bf_pack(h0_, h1_);
            Al2[(p2 + 1) * GST + mr] = bf_pack(l0_, l1_);
            bf_split(vw.x, h0_, l0_); bf_split(vw.y, h1_, l1_);
            Wh2[p2 * GST + mr]       = bf_pack(h0_, h1_);
            Wl2[p2 * GST + mr]       = bf_pack(l0_, l1_);
            bf_split(vw.z, h0_, l0_); bf_split(vw.w, h1_, l1_);
            Wh2[(p2 + 1) * GST + mr] = bf_pack(h0_, h1_);
            Wl2[(p2 + 1) * GST + mr] = bf_pack(l0_, l1_);
        }
        __syncthreads();

        #pragma unroll
        for (int kt = 0; kt < 2; kt++) {            // two k16 steps per chunk
            unsigned ah[4][4], al[4][4], bh[4][2], bl[4][2];
            const int ka = (kt * 8 + lt) * GST;
            const int kb = (kt * 8 + lt + 4) * GST;
            #pragma unroll
            for (int mt = 0; mt < 4; mt++) {
                const int mb = wm * 64 + mt * 16 + lg;
                ah[mt][0] = Ah2[ka + mb];     ah[mt][1] = Ah2[ka + mb + 8];
                ah[mt][2] = Ah2[kb + mb];     ah[mt][3] = Ah2[kb + mb + 8];
                al[mt][0] = Al2[ka + mb];     al[mt][1] = Al2[ka + mb + 8];
                al[mt][2] = Al2[kb + mb];     al[mt][3] = Al2[kb + mb + 8];
            }
            #pragma unroll
            for (int nt = 0; nt < 4; nt++) {
                const int nb = wn * 32 + nt * 8 + lg;
                bh[nt][0] = Wh2[ka + nb];     bh[nt][1] = Wh2[kb + nb];
                bl[nt][0] = Wl2[ka + nb];     bl[nt][1] = Wl2[kb + nb];
            }
            #pragma unroll
            for (int mt = 0; mt < 4; mt++)
                #pragma unroll
                for (int nt = 0; nt < 4; nt++)
                    mma_bf16(acc[mt][nt], ah[mt], bh[nt]);
            #pragma unroll
            for (int mt = 0; mt < 4; mt++)
                #pragma unroll
                for (int nt = 0; nt < 4; nt++)
                    mma_bf16(acc[mt][nt], al[mt], bh[nt]);
            #pragma unroll
            for (int mt = 0; mt < 4; mt++)
                #pragma unroll
                for (int nt = 0; nt < 4; nt++)
                    mma_bf16(acc[mt][nt], ah[mt], bl[nt]);
        }
    }

    #pragma unroll
    for (int mt = 0; mt < 4; mt++) {
        const int row = m0 + wm * 64 + mt * 16 + lg;
        #pragma unroll
        for (int nt = 0; nt < 4; nt++) {
            const int col = n0 + wn * 32 + nt * 8 + lt * 2;
            float2 bs = *reinterpret_cast<const float2*>(bias + col);
            float2 o0 = make_float2(acc[mt][nt][0] + bs.x, acc[mt][nt][1] + bs.y);
            float2 o1 = make_float2(acc[mt][nt][2] + bs.x, acc[mt][nt][3] + bs.y);
            *reinterpret_cast<float2*>(C + (size_t)row * G4 + col)       = o0;
            *reinterpret_cast<float2*>(C + (size_t)(row + 8) * G4 + col) = o1;
        }
    }
}

// Fused two-layer pipelined recurrence, bf16 tensor, 8 warps / 256 threads.
// Warps 0-3: load h0 fragments ONCE, feed BOTH Wh0 (->red0, L0 t=s) and the
// Wi1 y0-part (->red1 cols 0-3, L1 t=s-1). Warps 4-7: h1 part (->red1 4-7).
// Removes the duplicate h0 global reads that bound R15.
__global__ __launch_bounds__(NTHR, 1) void lstm_fused_kernel(
    const float* __restrict__ Wh0, const float* __restrict__ bh0,
    const float* __restrict__ Wi1, const float* __restrict__ bi1,
    const float* __restrict__ Wh1, const float* __restrict__ bh1,
    const float* __restrict__ i2h, float* __restrict__ yout,
    float* __restrict__ hc_out)
{
    extern __shared__ float sm[];
    unsigned* wf0h = reinterpret_cast<unsigned*>(sm);       // 4096 u32
    unsigned* wf0l = wf0h + 4096;                           // 4096
    unsigned* wf1h = wf0l + 4096;                           // 8192
    unsigned* wf1l = wf1h + 8192;                           // 8192
    float* red0 = sm + 24576;                               // 16*32*4
    float* red1 = red0 + 2048;                               // 16*32*8
    float* pres = red1 + 4096;                              // 512
    float* bs0  = pres + 512;                               // 16
    float* bs1  = bs0 + 16;                                 // 16
    float* cs0  = bs1 + 16;                                 // 128
    float* cs1  = cs0 + 128;                                // 128

    const int tid = threadIdx.x;
    const int bid = blockIdx.x;
    const int j0 = bid * JC;
    const int lane = tid & 31;
    const int gid = lane >> 2;       // 0..7
    const int tig = lane & 3;        // 0..3

    // ---- stage weights: bf16 hi/lo in B-fragment order ----
    for (int t = tid; t < 32 * 2 * 32; t += NTHR) {          // L0: 32 ktiles
        int kt = t >> 6, nt = (t >> 5) & 1, ln = t & 31;
        int rl = nt * 8 + (ln >> 2);
        int g = rl >> 2, jj = rl & 3;
        const float* wr = Wh0 + (size_t)(g * HH + j0 + jj) * HH;
        int kk = kt * 16 + (ln & 3) * 2;
        unsigned short h0_, l0_, h1_, l1_, h8_, l8_, h9_, l9_;
        bf_split(wr[kk],     h0_, l0_);
        bf_split(wr[kk + 1], h1_, l1_);
        bf_split(wr[kk + 8], h8_, l8_);
        bf_split(wr[kk + 9], h9_, l9_);
        int o = (kt * 2 + nt) * 64 + ln * 2;
        wf0h[o]     = bf_pack(h0_, h1_);
        wf0h[o + 1] = bf_pack(h8_, h9_);
        wf0l[o]     = bf_pack(l0_, l1_);
        wf0l[o + 1] = bf_pack(l8_, l9_);
    }
    for (int t = tid; t < 64 * 2 * 32; t += NTHR) {          // L1: 64 ktiles
        int kt = t >> 6, nt = (t >> 5) & 1, ln = t & 31;
        int rl = nt * 8 + (ln >> 2);
        int g = rl >> 2, jj = rl & 3;
        int kk = kt * 16 + (ln & 3) * 2;
        const float* wr = (kk < 512)
            ? Wi1 + (size_t)(g * HH + j0 + jj) * HH
            : Wh1 + (size_t)(g * HH + j0 + jj) * HH - 512;
        unsigned short h0_, l0_, h1_, l1_, h8_, l8_, h9_, l9_;
        bf_split(wr[kk],     h0_, l0_);
        bf_split(wr[kk + 1], h1_, l1_);
        bf_split(wr[kk + 8], h8_, l8_);
        bf_split(wr[kk + 9], h9_, l9_);
        int o = (kt * 2 + nt) * 64 + ln * 2;
        wf1h[o]     = bf_pack(h0_, h1_);
        wf1h[o + 1] = bf_pack(h8_, h9_);
        wf1l[o]     = bf_pack(l0_, l1_);
        wf1l[o + 1] = bf_pack(l8_, l9_);
    }
    if (tid < 16) {
        int gg = tid >> 2, jx = tid & 3;
        bs0[tid] = bh0[gg * HH + j0 + jx];
        bs1[tid] = bi1[gg * HH + j0 + jx] + bh1[gg * HH + j0 + jx];
    }
    if (tid < 128) { cs0[tid] = 0.f; cs1[tid] = 0.f; }
    __syncthreads();

    const int w = tid >> 5;          // warp 0..7
    float4* pres4 = reinterpret_cast<float4*>(pres);

    for (int s = 0; s <= TT; s++) {
        // coalesced i2h prefetch (L0 tail input)
        float4 preq = make_float4(0.f, 0.f, 0.f, 0.f);
        if (tid < 128 && s < TT) {
            const int b_ = tid & 31, g_ = tid >> 5;
            preq = __ldcg(reinterpret_cast<const float4*>(
                i2h + ((size_t)b_ * TT + s) * G4 + (g_ << 9) + j0));
        }

        // ---- tensor phase ----
        if (w < 4) {
            // A = h0(s-1) k-slice, used for BOTH Wh0 (L0) and Wi1 (L1 y0).
            const unsigned short* hh = g_h0h[s & 1];
            const unsigned short* hl = g_h0l[s & 1];
            const int kth = w * 8;
            const bool doL0 = (s < TT);
            const bool doL1 = (s >= 1);
            float c0[2][2][4], c1[2][2][4];
            #pragma unroll
            for (int mt = 0; mt < 2; mt++)
                #pragma unroll
                for (int nt = 0; nt < 2; nt++)
                    #pragma unroll
                    for (int i = 0; i < 4; i++) { c0[mt][nt][i] = 0.f; c1[mt][nt][i] = 0.f; }

            #pragma unroll
            for (int k = 0; k < 8; k++) {
                unsigned b0h[2][2], b0l[2][2], b1h[2][2], b1l[2][2];
                #pragma unroll
                for (int nt = 0; nt < 2; nt++) {
                    const int o = ((kth + k) * 2 + nt) * 64 + lane * 2;
                    if (doL0) {
                        uint2 vh = *reinterpret_cast<const uint2*>(wf0h + o);
                        uint2 vl = *reinterpret_cast<const uint2*>(wf0l + o);
                        b0h[nt][0] = vh.x; b0h[nt][1] = vh.y;
                        b0l[nt][0] = vl.x; b0l[nt][1] = vl.y;
                    }
                    if (doL1) {
                        uint2 vh = *reinterpret_cast<const uint2*>(wf1h + o);
                        uint2 vl = *reinterpret_cast<const uint2*>(wf1l + o);
                        b1h[nt][0] = vh.x; b1h[nt][1] = vh.y;
                        b1l[nt][0] = vl.x; b1l[nt][1] = vl.y;
                    }
                }
                const int kk = (kth + k) * 16 + tig * 2;
                #pragma unroll
                for (int mt = 0; mt < 2; mt++) {
                    const int o = (mt * 16 + gid) * HH + kk;
                    unsigned ah[4], al[4];
                    ah[0] = __ldcg(reinterpret_cast<const unsigned*>(hh + o));
                    ah[1] = __ldcg(reinterpret_cast<const unsigned*>(hh + o + 8 * HH));
                    ah[2] = __ldcg(reinterpret_cast<const unsigned*>(hh + o + 8));
                    ah[3] = __ldcg(reinterpret_cast<const unsigned*>(hh + o + 8 * HH + 8));
                    al[0] = __ldcg(reinterpret_cast<const unsigned*>(hl + o));
                    al[1] = __ldcg(reinterpret_cast<const unsigned*>(hl + o + 8 * HH));
                    al[2] = __ldcg(reinterpret_cast<const unsigned*>(hl + o + 8));
                    al[3] = __ldcg(reinterpret_cast<const unsigned*>(hl + o + 8 * HH + 8));
                    #pragma unroll
                    for (int nt = 0; nt < 2; nt++) {
                        if (doL0) {
                            mma_bf16(c0[mt][nt], ah, b0h[nt]);
                            mma_bf16(c0[mt][nt], al, b0h[nt]);
                            mma_bf16(c0[mt][nt], ah, b0l[nt]);
                        }
                        if (doL1) {
                            mma_bf16(c1[mt][nt], ah, b1h[nt]);
                            mma_bf16(c1[mt][nt], al, b1h[nt]);
                            mma_bf16(c1[mt][nt], ah, b1l[nt]);
                        }
                    }
                }
            }
            #pragma unroll
            for (int mt = 0; mt < 2; mt++) {
                const int b = mt * 16 + gid;
                #pragma unroll
                for (int nt = 0; nt < 2; nt++) {
                    const int rl = nt * 8 + tig * 2;
                    if (doL0) {
                        red0[(rl * 32 + b) * 4 + w]           = c0[mt][nt][0];
                        red0[((rl + 1) * 32 + b) * 4 + w]     = c0[mt][nt][1];
                        red0[(rl * 32 + b + 8) * 4 + w]       = c0[mt][nt][2];
                        red0[((rl + 1) * 32 + b + 8) * 4 + w] = c0[mt][nt][3];
                    }
                    if (doL1) {
                        red1[(rl * 32 + b) * 8 + w]           = c1[mt][nt][0];
                        red1[((rl + 1) * 32 + b) * 8 + w]     = c1[mt][nt][1];
                        red1[(rl * 32 + b + 8) * 8 + w]       = c1[mt][nt][2];
                        red1[((rl + 1) * 32 + b + 8) * 8 + w] = c1[mt][nt][3];
                    }
                }
            }
        } else if (s >= 1) {
            // warps 4-7: A = h1(s-2), B = Wh1 part (wf1 ktiles 32..63)
            const unsigned short* hh = g_h1h[(s - 1) & 1];
            const unsigned short* hl = g_h1l[(s - 1) & 1];
            const int kth = (w - 4) * 8;
            const int ktw = 32 + (w - 4) * 8;
            float c1[2][2][4];
            #pragma unroll
            for (int mt = 0; mt < 2; mt++)
                #pragma unroll
                for (int nt = 0; nt < 2; nt++)
                    #pragma unroll
                    for (int i = 0; i < 4; i++) c1[mt][nt][i] = 0.f;

            #pragma unroll
            for (int k = 0; k < 8; k++) {
                unsigned bh[2][2], bl[2][2];
                #pragma unroll
                for (int nt = 0; nt < 2; nt++) {
                    const int o = ((ktw + k) * 2 + nt) * 64 + lane * 2;
                    uint2 vh = *reinterpret_cast<const uint2*>(wf1h + o);
                    uint2 vl = *reinterpret_cast<const uint2*>(wf1l + o);
                    bh[nt][0] = vh.x; bh[nt][1] = vh.y;
                    bl[nt][0] = vl.x; bl[nt][1] = vl.y;
                }
                const int kk = (kth + k) * 16 + tig * 2;
                #pragma unroll
                for (int mt = 0; mt < 2; mt++) {
                    const int o = (mt * 16 + gid) * HH + kk;
                    unsigned ah[4], al[4];
                    ah[0] = __ldcg(reinterpret_cast<const unsigned*>(hh + o));
                    ah[1] = __ldcg(reinterpret_cast<const unsigned*>(hh + o + 8 * HH));
                    ah[2] = __ldcg(reinterpret_cast<const unsigned*>(hh + o + 8));
                    ah[3] = __ldcg(reinterpret_cast<const unsigned*>(hh + o + 8 * HH + 8));
                    al[0] = __ldcg(reinterpret_cast<const unsigned*>(hl + o));
                    al[1] = __ldcg(reinterpret_cast<const unsigned*>(hl + o + 8 * HH));
                    al[2] = __ldcg(reinterpret_cast<const unsigned*>(hl + o + 8));
                    al[3] = __ldcg(reinterpret_cast<const unsigned*>(hl + o + 8 * HH + 8));
                    #pragma unroll
                    for (int nt = 0; nt < 2; nt++) {
                        mma_bf16(c1[mt][nt], ah, bh[nt]);
                        mma_bf16(c1[mt][nt], al, bh[nt]);
                        mma_bf16(c1[mt][nt], ah, bl[nt]);
                    }
                }
            }
            #pragma unroll
            for (int mt = 0; mt < 2; mt++) {
                const int b = mt * 16 + gid;
                #pragma unroll
                for (int nt = 0; nt < 2; nt++) {
                    const int rl = nt * 8 + tig * 2;
                    red1[(rl * 32 + b) * 8 + w]           = c1[mt][nt][0];
                    red1[((rl + 1) * 32 + b) * 8 + w]     = c1[mt][nt][1];
                    red1[(rl * 32 + b + 8) * 8 + w]       = c1[mt][nt][2];
                    red1[((rl + 1) * 32 + b + 8) * 8 + w] = c1[mt][nt][3];
                }
            }
        }
        if (tid < 128 && s < TT) pres4[tid] = preq;
        __syncthreads();

        // ---- tails: tid<128 -> L0, tid in [128,256) -> L1 ----
        float   y_val = 0.f;
        size_t  y_idx = 0;
        bool    y_pend = false;

        if (tid < 128) {
            if (s < TT) {
                const int b = tid & 31, jj = tid >> 5;
                const int j = j0 + jj;
                float gate[4];
                #pragma unroll
                for (int g = 0; g < 4; g++) {
                    const int rr = g * 4 + jj;
                    float4 q0 = *reinterpret_cast<const float4*>(&red0[(rr * 32 + b) * 4]);
                    float pre = pres[(g * 32 + b) * 4 + jj];
                    gate[g] = ((q0.x + q0.y) + (q0.z + q0.w)) + pre + bs0[rr];
                }
                float ig = sigf(gate[0]);
                float fg = sigf(gate[1]);
                float cg = tanhf_(gate[2]);
                float og = sigf(gate[3]);
                float c_new = fmaf(fg, cs0[tid], ig * cg);
                float h_new = og * tanhf_(c_new);
                cs0[tid] = c_new;
                unsigned short hh_, hl_;
                bf_split(h_new, hh_, hl_);
                const int p = (s + 1) & 1;
                g_h0h[p][b * HH + j] = hh_;
                g_h0l[p][b * HH + j] = hl_;
                if (s == TT - 1) {
                    hc_out[(size_t)0 * BB * HH + b * HH + j] = h_new;
                    hc_out[(size_t)2 * BB * HH + b * HH + j] = c_new;
                }
            }
        } else {
            if (s >= 1) {
                const int tt_ = tid - 128;
                const int b = tt_ & 31, jj = tt_ >> 5;
                const int j = j0 + jj;
                const int t = s - 1;
                float gate[4];
                #pragma unroll
                for (int g = 0; g < 4; g++) {
                    const int rr = g * 4 + jj;
                    const float4* rp = reinterpret_cast<const float4*>(&red1[(rr * 32 + b) * 8]);
                    float4 q0 = rp[0], q1 = rp[1];
                    gate[g] = ((q0.x + q0.y) + (q0.z + q0.w))
                            + ((q1.x + q1.y) + (q1.z + q1.w)) + bs1[rr];
                }
                float ig = sigf(gate[0]);
                float fg = sigf(gate[1]);
                float cg = tanhf_(gate[2]);
                float og = sigf(gate[3]);
                float c_new = fmaf(fg, cs1[tt_], ig * cg);
                float h_new = og * tanhf_(c_new);
                cs1[tt_] = c_new;
                unsigned short hh_, hl_;
                bf_split(h_new, hh_, hl_);
                g_h1h[s & 1][b * HH + j] = hh_;
                g_h1l[s & 1][b * HH + j] = hl_;
                y_val = h_new;
                y_idx = ((size_t)b * TT + t) * HH + j;
                if (s < TT) {
                    y_pend = true;
                } else {
                    yout[y_idx] = h_new;
                }
                if (t == TT - 1) {
                    hc_out[(size_t)1 * BB * HH + b * HH + j] = h_new;
                    hc_out[(size_t)3 * BB * HH + b * HH + j] = c_new;
                }
            }
        }

        // ---- all-to-all flag barrier ----
        if (s < TT) {
            const unsigned e = (unsigned)(s + 1);
            __syncthreads();
            if (tid == 0)
                asm volatile("st.release.gpu.u32 [%0], %1;"
                             :: "l"(&g_flags[bid * 32]), "r"(e) : "memory");
            if (y_pend) yout[y_idx] = y_val;
            if (tid < NCTA) {
                unsigned v;
                do {
                    asm volatile("ld.acquire.gpu.u32 %0, [%1];"
                                 : "=r"(v) : "l"(&g_flags[tid * 32]) : "memory");
                } while (v < e);
            }
            __syncthreads();
        }
    }
}

extern "C" void kernel_launch(void* const* d_in, const int* in_sizes, int n_in,
                              void* d_out, int out_size)
{
    (void)in_sizes; (void)n_in; (void)out_size;
    const float* x   = (const float*)d_in[0];
    const float* Wi0 = (const float*)d_in[1];
    const float* bi0 = (const float*)d_in[2];
    const float* Wh0 = (const float*)d_in[3];
    const float* bh0 = (const float*)d_in[4];
    const float* Wi1 = (const float*)d_in[5];
    const float* bi1 = (const float*)d_in[6];
    const float* Wh1 = (const float*)d_in[7];
    const float* bh1 = (const float*)d_in[8];
    float* out = (float*)d_out;

    float* i2h_p;
    cudaGetSymbolAddress((void**)&i2h_p, g_i2h);

    const int SMEM_G = 4 * 16 * GST * (int)sizeof(unsigned);
    cudaFuncSetAttribute(gemm_bf16_kernel,
                         cudaFuncAttributeMaxDynamicSharedMemorySize, SMEM_G);

    const int SMEM = (24576 + 2048 + 4096 + 512 + 16 + 16 + 128 + 128)
                     * (int)sizeof(float);
    cudaFuncSetAttribute(lstm_fused_kernel,
                         cudaFuncAttributeMaxDynamicSharedMemorySize, SMEM);

    dim3 ggrid(G4 / 128, (BB * TT) / 128);
    float* hc = out + (size_t)BB * TT * HH;

    gemm_bf16_kernel<<<ggrid, 256, SMEM_G>>>(x, Wi0, bi0, i2h_p);
    init_state_kernel<<<64, 256>>>();
    lstm_fused_kernel<<<NCTA, NTHR, SMEM>>>(Wh0, bh0, Wi1, bi1, Wh1, bh1,
                                            i2h_p, out, hc);
}

// round 17
// speedup vs baseline: 1.2932x; 1.2932x over previous
#include <cuda_runtime.h>
#include <cuda_bf16.h>
#include <cstddef>

#define BB 32
#define TT 2048
#define DD 512
#define HH 512
#define G4 2048
#define NCTA 128
#define JC 4
#define NTHR 384
#define GST 136
#define HPITCH 260   // u32 pitch for smem h rows: 260 mod 32 = 4 -> conflict-free

// Scratch (device globals are the sanctioned allocation-free scratch)
__device__ float g_i2h[(size_t)BB * TT * G4];        // 512 MB, layer-0 i2h
__device__ unsigned short g_h0h[2][BB * HH];         // h0 bf16 hi, [b][k]
__device__ unsigned short g_h0l[2][BB * HH];         // h0 bf16 lo
__device__ unsigned short g_h1h[2][BB * HH];         // h1 bf16 hi
__device__ unsigned short g_h1l[2][BB * HH];         // h1 bf16 lo
__device__ unsigned g_flags[NCTA * 32];              // per-CTA arrival flags

__global__ void init_state_kernel() {
    int i = blockIdx.x * blockDim.x + threadIdx.x;
    if (i < BB * HH) {
        g_h0h[0][i] = 0; g_h0l[0][i] = 0;
        g_h1h[0][i] = 0; g_h1l[0][i] = 0;
    }
    if (i < NCTA * 32) g_flags[i] = 0u;
}

__device__ __forceinline__ float sigf(float x) { return 1.f / (1.f + __expf(-x)); }
__device__ __forceinline__ float tanhf_(float x) {
    x = fminf(15.f, fmaxf(-15.f, x));
    float e = __expf(2.f * x);
    return (e - 1.f) / (e + 1.f);
}

union BFU { __nv_bfloat16 b; unsigned short u; };
__device__ __forceinline__ void bf_split(float v, unsigned short& hi, unsigned short& lo) {
    BFU h; h.b = __float2bfloat16_rn(v);
    BFU l; l.b = __float2bfloat16_rn(v - __bfloat162float(h.b));
    hi = h.u; lo = l.u;
}
__device__ __forceinline__ unsigned bf_pack(unsigned short lo16, unsigned short hi16) {
    return (unsigned)lo16 | ((unsigned)hi16 << 16);
}

__device__ __forceinline__ void mma_bf16(float* d, const unsigned* a, const unsigned* b) {
    asm volatile(
        "mma.sync.aligned.m16n8k16.row.col.f32.bf16.bf16.f32 "
        "{%0,%1,%2,%3}, {%4,%5,%6,%7}, {%8,%9}, {%0,%1,%2,%3};"
        : "+f"(d[0]), "+f"(d[1]), "+f"(d[2]), "+f"(d[3])
        : "r"(a[0]), "r"(a[1]), "r"(a[2]), "r"(a[3]), "r"(b[0]), "r"(b[1]));
}

// C[M,2048] = A[M,512] @ W[2048,512]^T + bias via 3-term bf16 tensor MMA.
__global__ __launch_bounds__(256) void gemm_bf16_kernel(
    const float* __restrict__ A, const float* __restrict__ W,
    const float* __restrict__ bias, float* __restrict__ C)
{
    extern __shared__ unsigned gsmu[];
    unsigned* Ah2 = gsmu;
    unsigned* Al2 = Ah2 + 16 * GST;
    unsigned* Wh2 = Al2 + 16 * GST;
    unsigned* Wl2 = Wh2 + 16 * GST;

    const int tid  = threadIdx.x;
    const int lane = tid & 31;
    const int w    = tid >> 5;
    const int wm   = w >> 2;
    const int wn   = w & 3;
    const int lg   = lane >> 2;
    const int lt   = lane & 3;
    const int m0   = blockIdx.y * 128;
    const int n0   = blockIdx.x * 128;

    const int mr = tid >> 1;
    const int kq = (tid & 1) << 4;
    const float* Arow = A + (size_t)(m0 + mr) * DD;
    const float* Wrow = W + (size_t)(n0 + mr) * DD;

    float acc[4][4][4];
    #pragma unroll
    for (int mt = 0; mt < 4; mt++)
        #pragma unroll
        for (int nt = 0; nt < 4; nt++)
            #pragma unroll
            for (int i = 0; i < 4; i++) acc[mt][nt][i] = 0.f;

    for (int kc = 0; kc < DD; kc += 32) {
        __syncthreads();
        #pragma unroll
        for (int i = 0; i < 4; i++) {
            const int kk = kq + 4 * i;
            const int p2 = kk >> 1;
            float4 va = *reinterpret_cast<const float4*>(Arow + kc + kk);
            float4 vw = *reinterpret_cast<const float4*>(Wrow + kc + kk);
            unsigned short h0_, l0_, h1_, l1_;
            bf_split(va.x, h0_, l0_); bf_split(va.y, h1_, l1_);
            Ah2[p2 * GST + mr]       = bf_pack(h0_, h1_);
            Al2[p2 * GST + mr]       = bf_pack(l0_, l1_);
            bf_split(va.z, h0_, l0_); bf_split(va.w, h1_, l1_);
            Ah2[(p2 + 1) * GST + mr] = bf_pack(h0_, h1_);
            Al2[(p2 + 1) * GST + mr] = bf_pack(l0_, l1_);
            bf_split(vw.x, h0_, l0_); bf_split(vw.y, h1_, l1_);
            Wh2[p2 * GST + mr]       = bf_pack(h0_, h1_);
            Wl2[p2 * GST + mr]       = bf_pack(l0_, l1_);
            bf_split(vw.z, h0_, l0_); bf_split(vw.w, h1_, l1_);
            Wh2[(p2 + 1) * GST + mr] = bf_pack(h0_, h1_);
            Wl2[(p2 + 1) * GST + mr] = bf_pack(l0_, l1_);
        }
        __syncthreads();

        #pragma unroll
        for (int kt = 0; kt < 2; kt++) {
            unsigned ah[4][4], al[4][4], bh[4][2], bl[4][2];
            const int ka = (kt * 8 + lt) * GST;
            const int kb = (kt * 8 + lt + 4) * GST;
            #pragma unroll
            for (int mt = 0; mt < 4; mt++) {
                const int mb = wm * 64 + mt * 16 + lg;
                ah[mt][0] = Ah2[ka + mb];     ah[mt][1] = Ah2[ka + mb + 8];
                ah[mt][2] = Ah2[kb + mb];     ah[mt][3] = Ah2[kb + mb + 8];
                al[mt][0] = Al2[ka + mb];     al[mt][1] = Al2[ka + mb + 8];
                al[mt][2] = Al2[kb + mb];     al[mt][3] = Al2[kb + mb + 8];
            }
            #pragma unroll
            for (int nt = 0; nt < 4; nt++) {
                const int nb = wn * 32 + nt * 8 + lg;
                bh[nt][0] = Wh2[ka + nb];     bh[nt][1] = Wh2[kb + nb];
                bl[nt][0] = Wl2[ka + nb];     bl[nt][1] = Wl2[kb + nb];
            }
            #pragma unroll
            for (int mt = 0; mt < 4; mt++)
                #pragma unroll
                for (int nt = 0; nt < 4; nt++)
                    mma_bf16(acc[mt][nt], ah[mt], bh[nt]);
            #pragma unroll
            for (int mt = 0; mt < 4; mt++)
                #pragma unroll
                for (int nt = 0; nt < 4; nt++)
                    mma_bf16(acc[mt][nt], al[mt], bh[nt]);
            #pragma unroll
            for (int mt = 0; mt < 4; mt++)
                #pragma unroll
                for (int nt = 0; nt < 4; nt++)
                    mma_bf16(acc[mt][nt], ah[mt], bl[nt]);
        }
    }

    #pragma unroll
    for (int mt = 0; mt < 4; mt++) {
        const int row = m0 + wm * 64 + mt * 16 + lg;
        #pragma unroll
        for (int nt = 0; nt < 4; nt++) {
            const int col = n0 + wn * 32 + nt * 8 + lt * 2;
            float2 bs = *reinterpret_cast<const float2*>(bias + col);
            float2 o0 = make_float2(acc[mt][nt][0] + bs.x, acc[mt][nt][1] + bs.y);
            float2 o1 = make_float2(acc[mt][nt][2] + bs.x, acc[mt][nt][3] + bs.y);
            *reinterpret_cast<float2*>(C + (size_t)row * G4 + col)       = o0;
            *reinterpret_cast<float2*>(C + (size_t)(row + 8) * G4 + col) = o1;
        }
    }
}

// Fused two-layer pipelined recurrence, bf16 tensor, 12 warps (R15 balance).
// NEW: h0 hi/lo staged to smem each step (coalesced uint4), shared by warps
// 0-7; A-fragments come from conflict-free LDS (pitch 260 u32 -> banks
// 4*gid+tig, all 32 lanes distinct). h1 (warps 8-11) stays __ldcg.
__global__ __launch_bounds__(NTHR, 1) void lstm_fused_kernel(
    const float* __restrict__ Wh0, const float* __restrict__ bh0,
    const float* __restrict__ Wi1, const float* __restrict__ bi1,
    const float* __restrict__ Wh1, const float* __restrict__ bh1,
    const float* __restrict__ i2h, float* __restrict__ yout,
    float* __restrict__ hc_out)
{
    extern __shared__ float sm[];
    unsigned* wf0h = reinterpret_cast<unsigned*>(sm);       // 4096 u32
    unsigned* wf0l = wf0h + 4096;                           // 4096
    unsigned* wf1h = wf0l + 4096;                           // 8192
    unsigned* wf1l = wf1h + 8192;                           // 8192
    unsigned* hs0h = wf1l + 8192;                           // 32*260 = 8320
    unsigned* hs0l = hs0h + BB * HPITCH;                    // 8320
    float* red0 = reinterpret_cast<float*>(hs0l + BB * HPITCH);  // 2048
    float* red1 = red0 + 2048;                              // 4096
    float* pres = red1 + 4096;                              // 512
    float* bs0  = pres + 512;                               // 16
    float* bs1  = bs0 + 16;                                 // 16
    float* cs0  = bs1 + 16;                                 // 128
    float* cs1  = cs0 + 128;                                // 128

    const int tid = threadIdx.x;
    const int bid = blockIdx.x;
    const int j0 = bid * JC;
    const int lane = tid & 31;
    const int gid = lane >> 2;       // 0..7
    const int tig = lane & 3;        // 0..3

    // ---- stage weights: bf16 hi/lo in B-fragment order ----
    for (int t = tid; t < 32 * 2 * 32; t += NTHR) {          // L0: 32 ktiles
        int kt = t >> 6, nt = (t >> 5) & 1, ln = t & 31;
        int rl = nt * 8 + (ln >> 2);
        int g = rl >> 2, jj = rl & 3;
        const float* wr = Wh0 + (size_t)(g * HH + j0 + jj) * HH;
        int kk = kt * 16 + (ln & 3) * 2;
        unsigned short h0_, l0_, h1_, l1_, h8_, l8_, h9_, l9_;
        bf_split(wr[kk],     h0_, l0_);
        bf_split(wr[kk + 1], h1_, l1_);
        bf_split(wr[kk + 8], h8_, l8_);
        bf_split(wr[kk + 9], h9_, l9_);
        int o = (kt * 2 + nt) * 64 + ln * 2;
        wf0h[o]     = bf_pack(h0_, h1_);
        wf0h[o + 1] = bf_pack(h8_, h9_);
        wf0l[o]     = bf_pack(l0_, l1_);
        wf0l[o + 1] = bf_pack(l8_, l9_);
    }
    for (int t = tid; t < 64 * 2 * 32; t += NTHR) {          // L1: 64 ktiles
        int kt = t >> 6, nt = (t >> 5) & 1, ln = t & 31;
        int rl = nt * 8 + (ln >> 2);
        int g = rl >> 2, jj = rl & 3;
        int kk = kt * 16 + (ln & 3) * 2;
        const float* wr = (kk < 512)
            ? Wi1 + (size_t)(g * HH + j0 + jj) * HH
            : Wh1 + (size_t)(g * HH + j0 + jj) * HH - 512;
        unsigned short h0_, l0_, h1_, l1_, h8_, l8_, h9_, l9_;
        bf_split(wr[kk],     h0_, l0_);
        bf_split(wr[kk + 1], h1_, l1_);
        bf_split(wr[kk + 8], h8_, l8_);
        bf_split(wr[kk + 9], h9_, l9_);
        int o = (kt * 2 + nt) * 64 + ln * 2;
        wf1h[o]     = bf_pack(h0_, h1_);
        wf1h[o + 1] = bf_pack(h8_, h9_);
        wf1l[o]     = bf_pack(l0_, l1_);
        wf1l[o + 1] = bf_pack(l8_, l9_);
    }
    if (tid < 16) {
        int gg = tid >> 2, jx = tid & 3;
        bs0[tid] = bh0[gg * HH + j0 + jx];
        bs1[tid] = bi1[gg * HH + j0 + jx] + bh1[gg * HH + j0 + jx];
    }
    if (tid < 128) { cs0[tid] = 0.f; cs1[tid] = 0.f; }
    __syncthreads();

    const int w = tid >> 5;          // warp 0..11
    float4* pres4 = reinterpret_cast<float4*>(pres);

    for (int s = 0; s <= TT; s++) {
        // coalesced i2h prefetch (L0 tail input)
        float4 preq = make_float4(0.f, 0.f, 0.f, 0.f);
        if (tid < 128 && s < TT) {
            const int b_ = tid & 31, g_ = tid >> 5;
            preq = __ldcg(reinterpret_cast<const float4*>(
                i2h + ((size_t)b_ * TT + s) * G4 + (g_ << 9) + j0));
        }

        // ---- stage h0 hi/lo to smem (coalesced uint4, all 384 threads) ----
        {
            const uint4* srcH = reinterpret_cast<const uint4*>(g_h0h[s & 1]);
            const uint4* srcL = reinterpret_cast<const uint4*>(g_h0l[s & 1]);
            #pragma unroll
            for (int i = 0; i < 6; i++) {
                int idx = tid + i * NTHR;          // 2048 uint4 per matrix
                if (idx < 2048) {
                    int b = idx >> 6, q = idx & 63;
                    uint4 vh = __ldcg(&srcH[b * 64 + q]);
                    uint4 vl = __ldcg(&srcL[b * 64 + q]);
                    *reinterpret_cast<uint4*>(&hs0h[b * HPITCH + q * 4]) = vh;
                    *reinterpret_cast<uint4*>(&hs0l[b * HPITCH + q * 4]) = vl;
                }
            }
        }
        __syncthreads();

        // ---- tensor phase (R15 12-warp balance) ----
        {
            const unsigned *bfh = nullptr, *bfl = nullptr;
            const unsigned short *g1h = nullptr, *g1l = nullptr;
            int kth = 0, ktw = 0;
            bool active = false, fromSmem = true;
            if (w < 4) {                    // L0: A = h0 (smem)
                if (s < TT) {
                    active = true;
                    bfh = wf0h; bfl = wf0l;
                    kth = w * 8; ktw = w * 8;
                }
            } else if (s >= 1) {
                active = true;
                bfh = wf1h; bfl = wf1l;
                if (w < 8) {                // L1 y0-part: A = h0 (smem)
                    kth = (w - 4) * 8; ktw = (w - 4) * 8;
                } else {                    // L1 h1-part: A = h1 (__ldcg)
                    fromSmem = false;
                    g1h = g_h1h[(s - 1) & 1]; g1l = g_h1l[(s - 1) & 1];
                    kth = (w - 8) * 8; ktw = 32 + (w - 8) * 8;
                }
            }
            if (active) {
                float c[2][2][4];
                #pragma unroll
                for (int mt = 0; mt < 2; mt++)
                    #pragma unroll
                    for (int nt = 0; nt < 2; nt++)
                        #pragma unroll
                        for (int i = 0; i < 4; i++) c[mt][nt][i] = 0.f;

                #pragma unroll
                for (int k = 0; k < 8; k++) {
                    unsigned bh[2][2], bl[2][2];
                    #pragma unroll
                    for (int nt = 0; nt < 2; nt++) {
                        const int o = ((ktw + k) * 2 + nt) * 64 + lane * 2;
                        uint2 vh = *reinterpret_cast<const uint2*>(bfh + o);
                        uint2 vl = *reinterpret_cast<const uint2*>(bfl + o);
                        bh[nt][0] = vh.x; bh[nt][1] = vh.y;
                        bl[nt][0] = vl.x; bl[nt][1] = vl.y;
                    }
                    #pragma unroll
                    for (int mt = 0; mt < 2; mt++) {
                        unsigned ah[4], al[4];
                        if (fromSmem) {
                            const int pr = (kth + k) * 8 + tig;          // u32 pair
                            const int r0 = (mt * 16 + gid) * HPITCH;
                            const int r8 = (mt * 16 + gid + 8) * HPITCH;
                            ah[0] = hs0h[r0 + pr];
                            ah[1] = hs0h[r8 + pr];
                            ah[2] = hs0h[r0 + pr + 4];
                            ah[3] = hs0h[r8 + pr + 4];
                            al[0] = hs0l[r0 + pr];
                            al[1] = hs0l[r8 + pr];
                            al[2] = hs0l[r0 + pr + 4];
                            al[3] = hs0l[r8 + pr + 4];
                        } else {
                            const int kk = (kth + k) * 16 + tig * 2;
                            const int o = (mt * 16 + gid) * HH + kk;
                            ah[0] = __ldcg(reinterpret_cast<const unsigned*>(g1h + o));
                            ah[1] = __ldcg(reinterpret_cast<const unsigned*>(g1h + o + 8 * HH));
                            ah[2] = __ldcg(reinterpret_cast<const unsigned*>(g1h + o + 8));
                            ah[3] = __ldcg(reinterpret_cast<const unsigned*>(g1h + o + 8 * HH + 8));
                            al[0] = __ldcg(reinterpret_cast<const unsigned*>(g1l + o));
                            al[1] = __ldcg(reinterpret_cast<const unsigned*>(g1l + o + 8 * HH));
                            al[2] = __ldcg(reinterpret_cast<const unsigned*>(g1l + o + 8));
                            al[3] = __ldcg(reinterpret_cast<const unsigned*>(g1l + o + 8 * HH + 8));
                        }
                        #pragma unroll
                        for (int nt = 0; nt < 2; nt++) {
                            mma_bf16(c[mt][nt], ah, bh[nt]);
                            mma_bf16(c[mt][nt], al, bh[nt]);
                            mma_bf16(c[mt][nt], ah, bl[nt]);
                        }
                    }
                }
                #pragma unroll
                for (int mt = 0; mt < 2; mt++) {
                    const int b = mt * 16 + gid;
                    #pragma unroll
                    for (int nt = 0; nt < 2; nt++) {
                        const int rl = nt * 8 + tig * 2;
                        if (w < 4) {
                            red0[(rl * 32 + b) * 4 + w]           = c[mt][nt][0];
                            red0[((rl + 1) * 32 + b) * 4 + w]     = c[mt][nt][1];
                            red0[(rl * 32 + b + 8) * 4 + w]       = c[mt][nt][2];
                            red0[((rl + 1) * 32 + b + 8) * 4 + w] = c[mt][nt][3];
                        } else {
                            const int wc = w - 4;
                            red1[(rl * 32 + b) * 8 + wc]           = c[mt][nt][0];
                            red1[((rl + 1) * 32 + b) * 8 + wc]     = c[mt][nt][1];
                            red1[(rl * 32 + b + 8) * 8 + wc]       = c[mt][nt][2];
                            red1[((rl + 1) * 32 + b + 8) * 8 + wc] = c[mt][nt][3];
                        }
                    }
                }
            }
        }
        if (tid < 128 && s < TT) pres4[tid] = preq;
        __syncthreads();

        // ---- tails: tid<128 -> L0, tid in [128,256) -> L1 ----
        float   y_val = 0.f;
        size_t  y_idx = 0;
        bool    y_pend = false;

        if (tid < 128) {
            if (s < TT) {
                const int b = tid & 31, jj = tid >> 5;
                const int j = j0 + jj;
                float gate[4];
                #pragma unroll
                for (int g = 0; g < 4; g++) {
                    const int rr = g * 4 + jj;
                    float4 q0 = *reinterpret_cast<const float4*>(&red0[(rr * 32 + b) * 4]);
                    float pre = pres[(g * 32 + b) * 4 + jj];
                    gate[g] = ((q0.x + q0.y) + (q0.z + q0.w)) + pre + bs0[rr];
                }
                float ig = sigf(gate[0]);
                float fg = sigf(gate[1]);
                float cg = tanhf_(gate[2]);
                float og = sigf(gate[3]);
                float c_new = fmaf(fg, cs0[tid], ig * cg);
                float h_new = og * tanhf_(c_new);
                cs0[tid] = c_new;
                unsigned short hh_, hl_;
                bf_split(h_new, hh_, hl_);
                const int p = (s + 1) & 1;
                g_h0h[p][b * HH + j] = hh_;
                g_h0l[p][b * HH + j] = hl_;
                if (s == TT - 1) {
                    hc_out[(size_t)0 * BB * HH + b * HH + j] = h_new;
                    hc_out[(size_t)2 * BB * HH + b * HH + j] = c_new;
                }
            }
        } else if (tid < 256) {
            if (s >= 1) {
                const int tt_ = tid - 128;
                const int b = tt_ & 31, jj = tt_ >> 5;
                const int j = j0 + jj;
                const int t = s - 1;
                float gate[4];
                #pragma unroll
                for (int g = 0; g < 4; g++) {
                    const int rr = g * 4 + jj;
                    const float4* rp = reinterpret_cast<const float4*>(&red1[(rr * 32 + b) * 8]);
                    float4 q0 = rp[0], q1 = rp[1];
                    gate[g] = ((q0.x + q0.y) + (q0.z + q0.w))
                            + ((q1.x + q1.y) + (q1.z + q1.w)) + bs1[rr];
                }
                float ig = sigf(gate[0]);
                float fg = sigf(gate[1]);
                float cg = tanhf_(gate[2]);
                float og = sigf(gate[3]);
                float c_new = fmaf(fg, cs1[tt_], ig * cg);
                float h_new = og * tanhf_(c_new);
                cs1[tt_] = c_new;
                unsigned short hh_, hl_;
                bf_split(h_new, hh_, hl_);
                g_h1h[s & 1][b * HH + j] = hh_;
                g_h1l[s & 1][b * HH + j] = hl_;
                y_val = h_new;
                y_idx = ((size_t)b * TT + t) * HH + j;
                if (s < TT) {
                    y_pend = true;
                } else {
                    yout[y_idx] = h_new;
                }
                if (t == TT - 1) {
                    hc_out[(size_t)1 * BB * HH + b * HH + j] = h_new;
                    hc_out[(size_t)3 * BB * HH + b * HH + j] = c_new;
                }
            }
        }

        // ---- all-to-all flag barrier ----
        if (s < TT) {
            const unsigned e = (unsigned)(s + 1);
            __syncthreads();
            if (tid == 0)
                asm volatile("st.release.gpu.u32 [%0], %1;"
                             :: "l"(&g_flags[bid * 32]), "r"(e) : "memory");
            if (y_pend) yout[y_idx] = y_val;
            if (tid < NCTA) {
                unsigned v;
                do {
                    asm volatile("ld.acquire.gpu.u32 %0, [%1];"
                                 : "=r"(v) : "l"(&g_flags[tid * 32]) : "memory");
                } while (v < e);
            }
            __syncthreads();
        }
    }
}

extern "C" void kernel_launch(void* const* d_in, const int* in_sizes, int n_in,
                              void* d_out, int out_size)
{
    (void)in_sizes; (void)n_in; (void)out_size;
    const float* x   = (const float*)d_in[0];
    const float* Wi0 = (const float*)d_in[1];
    const float* bi0 = (const float*)d_in[2];
    const float* Wh0 = (const float*)d_in[3];
    const float* bh0 = (const float*)d_in[4];
    const float* Wi1 = (const float*)d_in[5];
    const float* bi1 = (const float*)d_in[6];
    const float* Wh1 = (const float*)d_in[7];
    const float* bh1 = (const float*)d_in[8];
    float* out = (float*)d_out;

    float* i2h_p;
    cudaGetSymbolAddress((void**)&i2h_p, g_i2h);

    const int SMEM_G = 4 * 16 * GST * (int)sizeof(unsigned);
    cudaFuncSetAttribute(gemm_bf16_kernel,
                         cudaFuncAttributeMaxDynamicSharedMemorySize, SMEM_G);

    const int SMEM = (24576 + 2 * BB * HPITCH + 2048 + 4096 + 512
                      + 16 + 16 + 128 + 128) * (int)sizeof(float);
    cudaFuncSetAttribute(lstm_fused_kernel,
                         cudaFuncAttributeMaxDynamicSharedMemorySize, SMEM);

    dim3 ggrid(G4 / 128, (BB * TT) / 128);
    float* hc = out + (size_t)BB * TT * HH;

    gemm_bf16_kernel<<<ggrid, 256, SMEM_G>>>(x, Wi0, bi0, i2h_p);
    init_state_kernel<<<64, 256>>>();
    lstm_fused_kernel<<<NCTA, NTHR, SMEM>>>(Wh0, bh0, Wi1, bi1, Wh1, bh1,
                                            i2h_p, out, hc);
}